// round 7
// baseline (speedup 1.0000x reference)
#include <cuda_runtime.h>
#include <cuda_bf16.h>
#include <cstdint>
#include <math.h>

// KMeansClusteringLoss via warp-specialized bf16 HMMA pipeline.
//   cost(l,c) = |mu_c|^2 - 2 <z_l, mu_c>,  d(l) = sqrt(max(|z_l|^2 + min_c cost, 0))
//   out = mean_l d(l)
//
// R7: producers are pure LDG->cvt->STS (no shfl z2); consumers compute |z|^2
// from the A fragments already in registers (cheap, overlaps MMA stalls).

#define KDIM  128
#define CDIM  512
#define MT    128          // z rows per tile
#define NTHREADS 512       // warps 0-7 consumers, 8-15 producers
#define NQ    256          // centroids per consumer warp

#define STRIDE_B 272       // 128 bf16 (256B) + 16B pad -> conflict-free LDSM

// dynamic smem layout (bytes)
#define SM_MU    0                          // 512 x 272 = 139264
#define SM_Z0    139264                     // 128 x 272 = 34816
#define SM_Z1    174080                     // 128 x 272 = 34816
#define SM_M2    208896                     // 512 f32
#define SM_Z2    210944                     // 128 f32
#define SM_MH    211456                     // 128 x 2 f32
#define SM_RED   212480                     // 8 f32
#define SM_PT    212512                     // 2 ints (tile ids)
#define SMEM_BYTES 212544

__device__ float g_sum;
__device__ unsigned int g_cnt;
__device__ unsigned int g_tile;
__device__ __align__(16) __nv_bfloat16 g_mu_bf[CDIM * KDIM];
__device__ float g_m2[CDIM];

// ---------------- helpers ----------------
__device__ __forceinline__ uint32_t smem_u32(const void* p) {
    uint32_t a;
    asm("{ .reg .u64 t; cvta.to.shared.u64 t, %1; cvt.u32.u64 %0, t; }" : "=r"(a) : "l"(p));
    return a;
}
__device__ __forceinline__ void ldsm_x4(uint32_t& r0, uint32_t& r1, uint32_t& r2, uint32_t& r3,
                                        uint32_t addr) {
    asm volatile("ldmatrix.sync.aligned.m8n8.x4.shared.b16 {%0,%1,%2,%3}, [%4];"
                 : "=r"(r0), "=r"(r1), "=r"(r2), "=r"(r3) : "r"(addr));
}
__device__ __forceinline__ void mma_bf16(float* d, const uint32_t* a,
                                         uint32_t b0, uint32_t b1) {
    asm volatile(
        "mma.sync.aligned.m16n8k16.row.col.f32.bf16.bf16.f32 "
        "{%0,%1,%2,%3}, {%4,%5,%6,%7}, {%8,%9}, {%0,%1,%2,%3};"
        : "+f"(d[0]), "+f"(d[1]), "+f"(d[2]), "+f"(d[3])
        : "r"(a[0]), "r"(a[1]), "r"(a[2]), "r"(a[3]), "r"(b0), "r"(b1));
}
#define BAR_SYNC(id, cnt)   asm volatile("bar.sync %0, %1;"   :: "r"(id), "r"(cnt) : "memory")
#define BAR_ARRIVE(id, cnt) asm volatile("bar.arrive %0, %1;" :: "r"(id), "r"(cnt) : "memory")

// Fill a z tile: global fp32 -> bf16 packed smem (no reductions).
__device__ __forceinline__ void fill_z(const float* __restrict__ z, int tile,
                                       char* smem, int zoff, int t, int nthr) {
    const size_t m0 = (size_t)tile * MT;
    const int iters = (MT * 16) / nthr;    // chunks of 8 floats
    #pragma unroll
    for (int it = 0; it < iters; it++) {
        int idx = t + it * nthr;
        int row = idx >> 4, kc = idx & 15;
        const float4* p = reinterpret_cast<const float4*>(z + (m0 + row) * KDIM + kc * 8);
        float4 v0 = p[0], v1 = p[1];
        __nv_bfloat162 b0 = __floats2bfloat162_rn(v0.x, v0.y);
        __nv_bfloat162 b1 = __floats2bfloat162_rn(v0.z, v0.w);
        __nv_bfloat162 b2 = __floats2bfloat162_rn(v1.x, v1.y);
        __nv_bfloat162 b3 = __floats2bfloat162_rn(v1.z, v1.w);
        uint4 q;
        q.x = *reinterpret_cast<uint32_t*>(&b0);
        q.y = *reinterpret_cast<uint32_t*>(&b1);
        q.z = *reinterpret_cast<uint32_t*>(&b2);
        q.w = *reinterpret_cast<uint32_t*>(&b3);
        *reinterpret_cast<uint4*>(smem + zoff + row * STRIDE_B + kc * 16) = q;
    }
}

// ---------------- prologue: mu fp32 -> bf16, m2, zero accumulators ----------------
__global__ void km_prep(const float* __restrict__ mu) {
    if (blockIdx.x == 0 && threadIdx.x == 0) { g_sum = 0.0f; g_cnt = 0u; g_tile = 0u; }
    int warp = (blockIdx.x * blockDim.x + threadIdx.x) >> 5;
    int lane = threadIdx.x & 31;
    if (warp >= CDIM) return;

    float4 v = reinterpret_cast<const float4*>(mu + warp * KDIM)[lane];
    __nv_bfloat162 p0 = __floats2bfloat162_rn(v.x, v.y);
    __nv_bfloat162 p1 = __floats2bfloat162_rn(v.z, v.w);
    reinterpret_cast<__nv_bfloat162*>(g_mu_bf + warp * KDIM)[lane * 2 + 0] = p0;
    reinterpret_cast<__nv_bfloat162*>(g_mu_bf + warp * KDIM)[lane * 2 + 1] = p1;

    float a0 = __bfloat162float(p0.x), a1 = __bfloat162float(p0.y);
    float a2 = __bfloat162float(p1.x), a3 = __bfloat162float(p1.y);
    float s = a0 * a0 + a1 * a1 + a2 * a2 + a3 * a3;
    #pragma unroll
    for (int o = 16; o > 0; o >>= 1) s += __shfl_down_sync(0xffffffffu, s, o);
    if (lane == 0) g_m2[warp] = s;
}

// ---------------- persistent warp-specialized kernel ----------------
__global__ void __launch_bounds__(NTHREADS, 1) km_main(
    const float* __restrict__ z, float* __restrict__ out, int L, int ntiles)
{
    extern __shared__ char smem[];
    const uint32_t sbase = smem_u32(smem);
    float* m2s  = reinterpret_cast<float*>(smem + SM_M2);
    float* z2s  = reinterpret_cast<float*>(smem + SM_Z2);
    float* mh   = reinterpret_cast<float*>(smem + SM_MH);
    float* red  = reinterpret_cast<float*>(smem + SM_RED);
    int* ptile  = reinterpret_cast<int*>(smem + SM_PT);

    const int tid  = threadIdx.x;
    const int wid  = tid >> 5;
    const int lane = tid & 31;

    // ---- prologue: steal first tile, load mu + m2, fill buf0 ----
    if (tid == 0) ptile[0] = (int)atomicAdd(&g_tile, 1u);   // grid <= ntiles, valid

    for (int idx = tid; idx < CDIM * 16; idx += NTHREADS) {  // 16B chunks
        int c = idx >> 4, kc = idx & 15;
        uint4 q = reinterpret_cast<const uint4*>(g_mu_bf)[idx];
        *reinterpret_cast<uint4*>(smem + SM_MU + c * STRIDE_B + kc * 16) = q;
    }
    for (int i = tid; i < CDIM; i += NTHREADS) m2s[i] = g_m2[i];
    __syncthreads();

    fill_z(z, ptile[0], smem, SM_Z0, tid, NTHREADS);
    __syncthreads();

    if (wid >= 8) {
        // ================= PRODUCER (warps 8-15) =================
        const int ptid = tid - 256;
        for (int i = 1;; i++) {
            const int p = i & 1;
            if (i >= 2) BAR_SYNC(3 + p, 512);                 // wait buffer empty
            if (ptid == 0) {
                int t = (int)atomicAdd(&g_tile, 1u);
                ptile[p] = (t < ntiles) ? t : -1;
            }
            BAR_SYNC(6, 256);                                  // producers: ptile visible
            const int t = ptile[p];
            if (t >= 0)
                fill_z(z, t, smem, p ? SM_Z1 : SM_Z0, ptid, 256);
            __threadfence_block();
            BAR_ARRIVE(1 + p, 512);                            // signal full
            if (t < 0) break;
        }
    } else {
        // ================= CONSUMER (warps 0-7) =================
        const int tg   = lane & 3;          // col pair within n8
        const int g    = lane >> 2;         // row within m16 half
        const int rw   = wid & 3;           // row-group (m32)
        const int nh   = wid >> 2;          // centroid half (0/1)
        const int r0   = rw * 32;
        const int nbase = nh * NQ;

        const uint32_t bb = sbase + SM_MU
                          + (lane & 7) * STRIDE_B
                          + (((lane >> 3) & 1) ? 16u : 0u)
                          + (lane >> 4) * 8 * STRIDE_B
                          + nbase * STRIDE_B;

        for (int i = 0;; i++) {
            const int p = i & 1;
            if (i >= 1) BAR_SYNC(1 + p, 512);                  // wait buffer full
            const int t = ptile[p];
            if (t < 0) break;
            const uint32_t zb = sbase + (p ? SM_Z1 : SM_Z0);

            // ---- A fragments: m32 x K128 register-resident ----
            uint32_t A[2][8][4];
            {
                const uint32_t ab = zb + (lane & 15) * STRIDE_B
                                  + ((lane & 16) ? 16u : 0u) + r0 * STRIDE_B;
                #pragma unroll
                for (int rg = 0; rg < 2; rg++)
                    #pragma unroll
                    for (int kk = 0; kk < 8; kk++)
                        ldsm_x4(A[rg][kk][0], A[rg][kk][1], A[rg][kk][2], A[rg][kk][3],
                                ab + rg * 16 * STRIDE_B + kk * 32);
            }

            // ---- |z|^2 for this warp's 4 rows from the A fragments ----
            // fragment spec: a0,a2 -> row (r0+16rg+g); a1,a3 -> row (+8);
            // quad (tg=0..3) covers the k dimension.
            {
                float z2a[4] = {0.f, 0.f, 0.f, 0.f};
                #pragma unroll
                for (int rg = 0; rg < 2; rg++)
                    #pragma unroll
                    for (int kk = 0; kk < 8; kk++)
                        #pragma unroll
                        for (int e = 0; e < 4; e++) {
                            uint32_t u = A[rg][kk][e];
                            float lo = __uint_as_float(u << 16);
                            float hi = __uint_as_float(u & 0xffff0000u);
                            int r = rg * 2 + (e & 1);
                            z2a[r] = fmaf(lo, lo, z2a[r]);
                            z2a[r] = fmaf(hi, hi, z2a[r]);
                        }
                #pragma unroll
                for (int q = 0; q < 4; q++) {
                    z2a[q] += __shfl_xor_sync(0xffffffffu, z2a[q], 1);
                    z2a[q] += __shfl_xor_sync(0xffffffffu, z2a[q], 2);
                }
                if (tg == 0 && nh == 0) {
                    z2s[r0 + g]      = z2a[0];
                    z2s[r0 + g + 8]  = z2a[1];
                    z2s[r0 + g + 16] = z2a[2];
                    z2s[r0 + g + 24] = z2a[3];
                }
            }

            // ---- 256 centroids: 16 iters of n16, 4 indep chains each ----
            float mn[4] = {INFINITY, INFINITY, INFINITY, INFINITY};
            #pragma unroll 1
            for (int nt = 0; nt < NQ / 16; nt++) {
                float acc[2][2][4] = {};
                const uint32_t ba = bb + nt * 16 * STRIDE_B;
                #pragma unroll
                for (int kk = 0; kk < 8; kk++) {
                    uint32_t b0, b1, b2, b3;
                    ldsm_x4(b0, b1, b2, b3, ba + kk * 32);
                    mma_bf16(acc[0][0], A[0][kk], b0, b1);
                    mma_bf16(acc[0][1], A[0][kk], b2, b3);
                    mma_bf16(acc[1][0], A[1][kk], b0, b1);
                    mma_bf16(acc[1][1], A[1][kk], b2, b3);
                }
                const int n0 = nbase + nt * 16;
                #pragma unroll
                for (int c = 0; c < 2; c++) {
                    float2 m = *reinterpret_cast<const float2*>(&m2s[n0 + 8 * c + 2 * tg]);
                    #pragma unroll
                    for (int rg = 0; rg < 2; rg++) {
                        mn[rg * 2 + 0] = fminf(mn[rg * 2 + 0], fmaf(-2.0f, acc[rg][c][0], m.x));
                        mn[rg * 2 + 0] = fminf(mn[rg * 2 + 0], fmaf(-2.0f, acc[rg][c][1], m.y));
                        mn[rg * 2 + 1] = fminf(mn[rg * 2 + 1], fmaf(-2.0f, acc[rg][c][2], m.x));
                        mn[rg * 2 + 1] = fminf(mn[rg * 2 + 1], fmaf(-2.0f, acc[rg][c][3], m.y));
                    }
                }
            }

            // ---- min across the 4 threads sharing each row ----
            #pragma unroll
            for (int q = 0; q < 4; q++) {
                mn[q] = fminf(mn[q], __shfl_xor_sync(0xffffffffu, mn[q], 1));
                mn[q] = fminf(mn[q], __shfl_xor_sync(0xffffffffu, mn[q], 2));
            }
            if (tg == 0) {
                mh[(r0 + g)      * 2 + nh] = mn[0];
                mh[(r0 + g + 8)  * 2 + nh] = mn[1];
                mh[(r0 + g + 16) * 2 + nh] = mn[2];
                mh[(r0 + g + 24) * 2 + nh] = mn[3];
            }
            BAR_SYNC(5, 256);                                  // consumers only

            float s = 0.0f;
            if (tid < MT) {
                float m = fminf(mh[tid * 2 + 0], mh[tid * 2 + 1]);
                s = sqrtf(fmaxf(z2s[tid] + m, 0.0f));
            }
            #pragma unroll
            for (int o = 16; o > 0; o >>= 1) s += __shfl_down_sync(0xffffffffu, s, o);
            if (lane == 0) red[wid] = s;
            BAR_SYNC(5, 256);

            if (tid == 0) {
                float tt = red[0] + red[1] + red[2] + red[3];
                atomicAdd(&g_sum, tt);
                __threadfence();
                unsigned int c = atomicAdd(&g_cnt, 1u);
                if (c == (unsigned int)(ntiles - 1))
                    out[0] = (*(volatile float*)&g_sum) / (float)L;
            }
            BAR_ARRIVE(3 + p, 512);                            // signal empty
        }
    }
}

extern "C" void kernel_launch(void* const* d_in, const int* in_sizes, int n_in,
                              void* d_out, int out_size) {
    const float* z  = (const float*)d_in[0];
    const float* mu = (const float*)d_in[1];
    float* out = (float*)d_out;

    int L = in_sizes[0] / KDIM;   // 65536
    int ntiles = L / MT;          // 512

    static int nsm = 0;
    if (nsm == 0) {
        cudaDeviceGetAttribute(&nsm, cudaDevAttrMultiProcessorCount, 0);
        cudaFuncSetAttribute(km_main, cudaFuncAttributeMaxDynamicSharedMemorySize, SMEM_BYTES);
    }
    int grid = (ntiles < nsm) ? ntiles : nsm;

    km_prep<<<64, 256>>>(mu);
    km_main<<<grid, NTHREADS, SMEM_BYTES>>>(z, out, L, ntiles);
}

// round 8
// speedup vs baseline: 1.0536x; 1.0536x over previous
#include <cuda_runtime.h>
#include <cuda_bf16.h>
#include <cstdint>
#include <math.h>

// KMeansClusteringLoss via warp-specialized bf16 HMMA pipeline (single kernel).
//   cost(l,c) = |mu_c|^2 - 2 <z_l, mu_c>,  d(l) = sqrt(max(|z_l|^2 + min_c cost, 0))
//   out = mean_l d(l)
//
// R8: single-kernel (per-CTA mu convert + m2, self-cleaning globals);
// producer z2 as cheap smem second pass (1 shfl/thread); 1-barrier epilogue
// with per-warp global atomics; 8 k-split accumulator chains + B prefetch.

#define KDIM  128
#define CDIM  512
#define MT    128
#define NTHREADS 512       // warps 0-7 consumers, 8-15 producers
#define NQ    256          // centroids per consumer warp

#define STRIDE_B 272       // 128 bf16 (256B) + 16B pad -> conflict-free LDSM

// dynamic smem layout (bytes)
#define SM_MU    0                          // 512 x 272 = 139264
#define SM_Z0    139264                     // 128 x 272
#define SM_Z1    174080                     // 128 x 272
#define SM_M2    208896                     // 512 f32
#define SM_Z2_0  210944                     // 128 f32
#define SM_Z2_1  211456                     // 128 f32
#define SM_MH0   211968                     // 128 x 2 f32
#define SM_MH1   212992                     // 128 x 2 f32
#define SM_PT    214016                     // 2 ints
#define SMEM_BYTES 214048

__device__ float g_sum;            // zero-init at load; self-cleaned each run
__device__ unsigned int g_cnt;
__device__ unsigned int g_tile;

// ---------------- helpers ----------------
__device__ __forceinline__ uint32_t smem_u32(const void* p) {
    uint32_t a;
    asm("{ .reg .u64 t; cvta.to.shared.u64 t, %1; cvt.u32.u64 %0, t; }" : "=r"(a) : "l"(p));
    return a;
}
__device__ __forceinline__ void ldsm_x4(uint32_t& r0, uint32_t& r1, uint32_t& r2, uint32_t& r3,
                                        uint32_t addr) {
    asm volatile("ldmatrix.sync.aligned.m8n8.x4.shared.b16 {%0,%1,%2,%3}, [%4];"
                 : "=r"(r0), "=r"(r1), "=r"(r2), "=r"(r3) : "r"(addr));
}
__device__ __forceinline__ void mma_bf16(float* d, const uint32_t* a,
                                         uint32_t b0, uint32_t b1) {
    asm volatile(
        "mma.sync.aligned.m16n8k16.row.col.f32.bf16.bf16.f32 "
        "{%0,%1,%2,%3}, {%4,%5,%6,%7}, {%8,%9}, {%0,%1,%2,%3};"
        : "+f"(d[0]), "+f"(d[1]), "+f"(d[2]), "+f"(d[3])
        : "r"(a[0]), "r"(a[1]), "r"(a[2]), "r"(a[3]), "r"(b0), "r"(b1));
}
#define BAR_SYNC(id, cnt)   asm volatile("bar.sync %0, %1;"   :: "r"(id), "r"(cnt) : "memory")
#define BAR_ARRIVE(id, cnt) asm volatile("bar.arrive %0, %1;" :: "r"(id), "r"(cnt) : "memory")

// Fill a z tile: global fp32 -> bf16 packed smem (no reductions).
__device__ __forceinline__ void fill_z(const float* __restrict__ z, int tile,
                                       char* smem, int zoff, int t, int nthr) {
    const size_t m0 = (size_t)tile * MT;
    const int iters = (MT * 16) / nthr;
    #pragma unroll
    for (int it = 0; it < iters; it++) {
        int idx = t + it * nthr;
        int row = idx >> 4, kc = idx & 15;
        const float4* p = reinterpret_cast<const float4*>(z + (m0 + row) * KDIM + kc * 8);
        float4 v0 = p[0], v1 = p[1];
        __nv_bfloat162 b0 = __floats2bfloat162_rn(v0.x, v0.y);
        __nv_bfloat162 b1 = __floats2bfloat162_rn(v0.z, v0.w);
        __nv_bfloat162 b2 = __floats2bfloat162_rn(v1.x, v1.y);
        __nv_bfloat162 b3 = __floats2bfloat162_rn(v1.z, v1.w);
        uint4 q;
        q.x = *reinterpret_cast<uint32_t*>(&b0);
        q.y = *reinterpret_cast<uint32_t*>(&b1);
        q.z = *reinterpret_cast<uint32_t*>(&b2);
        q.w = *reinterpret_cast<uint32_t*>(&b3);
        *reinterpret_cast<uint4*>(smem + zoff + row * STRIDE_B + kc * 16) = q;
    }
}

// |z|^2 second pass over a filled tile: 256 threads, 2 per row, 1 shfl.
__device__ __forceinline__ void z2_pass(const char* smem, int zoff, float* z2buf, int pt) {
    const int row = pt >> 1;
    const int half = pt & 1;
    float s = 0.0f;
    #pragma unroll
    for (int j = 0; j < 8; j++) {
        uint4 q = *reinterpret_cast<const uint4*>(smem + zoff + row * STRIDE_B
                                                  + half * 128 + j * 16);
        uint32_t u[4] = {q.x, q.y, q.z, q.w};
        #pragma unroll
        for (int e = 0; e < 4; e++) {
            float lo = __uint_as_float(u[e] << 16);
            float hi = __uint_as_float(u[e] & 0xffff0000u);
            s = fmaf(lo, lo, s);
            s = fmaf(hi, hi, s);
        }
    }
    s += __shfl_xor_sync(0xffffffffu, s, 1);     // pt parity == lane parity
    if (half == 0) z2buf[row] = s;
}

// ---------------- persistent warp-specialized kernel ----------------
__global__ void __launch_bounds__(NTHREADS, 1) km_main(
    const float* __restrict__ z, const float* __restrict__ mu,
    float* __restrict__ out, int L, int ntiles, int grid)
{
    extern __shared__ char smem[];
    const uint32_t sbase = smem_u32(smem);
    float* m2s = reinterpret_cast<float*>(smem + SM_M2);
    float* z2b[2] = { reinterpret_cast<float*>(smem + SM_Z2_0),
                      reinterpret_cast<float*>(smem + SM_Z2_1) };
    float* mhb[2] = { reinterpret_cast<float*>(smem + SM_MH0),
                      reinterpret_cast<float*>(smem + SM_MH1) };
    int* ptile = reinterpret_cast<int*>(smem + SM_PT);

    const int tid  = threadIdx.x;
    const int wid  = tid >> 5;
    const int lane = tid & 31;

    // ---- prologue: steal tile 0; convert mu fp32->bf16 into smem; m2; fill buf0 ----
    if (tid == 0) ptile[0] = (int)atomicAdd(&g_tile, 1u);

    #pragma unroll
    for (int it = 0; it < 16; it++) {            // 8192 chunks of 16B (bf16 out)
        int idx = tid + it * NTHREADS;
        int row = idx >> 4, kc = idx & 15;
        const float4* p = reinterpret_cast<const float4*>(mu + row * KDIM + kc * 8);
        float4 v0 = p[0], v1 = p[1];
        __nv_bfloat162 b0 = __floats2bfloat162_rn(v0.x, v0.y);
        __nv_bfloat162 b1 = __floats2bfloat162_rn(v0.z, v0.w);
        __nv_bfloat162 b2 = __floats2bfloat162_rn(v1.x, v1.y);
        __nv_bfloat162 b3 = __floats2bfloat162_rn(v1.z, v1.w);
        uint4 q;
        q.x = *reinterpret_cast<uint32_t*>(&b0);
        q.y = *reinterpret_cast<uint32_t*>(&b1);
        q.z = *reinterpret_cast<uint32_t*>(&b2);
        q.w = *reinterpret_cast<uint32_t*>(&b3);
        *reinterpret_cast<uint4*>(smem + SM_MU + row * STRIDE_B + kc * 16) = q;
    }
    __syncthreads();

    // m2 per centroid from the bf16 values (thread t -> row t)
    {
        float s = 0.0f;
        #pragma unroll
        for (int j = 0; j < 16; j++) {
            uint4 q = *reinterpret_cast<const uint4*>(smem + SM_MU + tid * STRIDE_B + j * 16);
            uint32_t u[4] = {q.x, q.y, q.z, q.w};
            #pragma unroll
            for (int e = 0; e < 4; e++) {
                float lo = __uint_as_float(u[e] << 16);
                float hi = __uint_as_float(u[e] & 0xffff0000u);
                s = fmaf(lo, lo, s);
                s = fmaf(hi, hi, s);
            }
        }
        m2s[tid] = s;
    }

    fill_z(z, ptile[0], smem, SM_Z0, tid, NTHREADS);
    __syncthreads();
    if (tid < 256) z2_pass(smem, SM_Z0, z2b[0], tid);
    __syncthreads();

    if (wid >= 8) {
        // ================= PRODUCER (warps 8-15) =================
        const int ptid = tid - 256;
        for (int i = 1;; i++) {
            const int p = i & 1;
            if (i >= 2) BAR_SYNC(3 + p, 512);                 // wait buffer empty
            if (ptid == 0) {
                int t = (int)atomicAdd(&g_tile, 1u);
                ptile[p] = (t < ntiles) ? t : -1;
            }
            BAR_SYNC(6, 256);                                  // ptile visible
            const int t = ptile[p];
            if (t >= 0) {
                const int zoff = p ? SM_Z1 : SM_Z0;
                fill_z(z, t, smem, zoff, ptid, 256);
                BAR_SYNC(6, 256);                              // drain STS before z2 reads
                z2_pass(smem, zoff, z2b[p], ptid);
            }
            __threadfence_block();
            BAR_ARRIVE(1 + p, 512);                            // signal full
            if (t < 0) break;
        }
    } else {
        // ================= CONSUMER (warps 0-7) =================
        const int tg   = lane & 3;
        const int g    = lane >> 2;
        const int rw   = wid & 3;           // row-group (m32)
        const int nh   = wid >> 2;          // centroid half (0/1)
        const int r0   = rw * 32;
        const int nbase = nh * NQ;

        const uint32_t bb = sbase + SM_MU
                          + (lane & 7) * STRIDE_B
                          + (((lane >> 3) & 1) ? 16u : 0u)
                          + (lane >> 4) * 8 * STRIDE_B
                          + nbase * STRIDE_B;

        for (int i = 0;; i++) {
            const int p = i & 1;
            if (i >= 1) BAR_SYNC(1 + p, 512);                  // wait buffer full
            const int t = ptile[p];
            if (t < 0) break;
            const uint32_t zb = sbase + (p ? SM_Z1 : SM_Z0);
            float* mhp = mhb[p];

            // ---- A fragments: m32 x K128 register-resident ----
            uint32_t A[2][8][4];
            {
                const uint32_t ab = zb + (lane & 15) * STRIDE_B
                                  + ((lane & 16) ? 16u : 0u) + r0 * STRIDE_B;
                #pragma unroll
                for (int rg = 0; rg < 2; rg++)
                    #pragma unroll
                    for (int kk = 0; kk < 8; kk++)
                        ldsm_x4(A[rg][kk][0], A[rg][kk][1], A[rg][kk][2], A[rg][kk][3],
                                ab + rg * 16 * STRIDE_B + kk * 32);
            }

            // ---- 256 centroids: 16 iters of n16; 8 k-split chains; B prefetch ----
            float mn[4] = {INFINITY, INFINITY, INFINITY, INFINITY};
            #pragma unroll 1
            for (int nt = 0; nt < NQ / 16; nt++) {
                float acc[2][2][2][4] = {};      // [rg][cpair][khalf][4]
                const uint32_t ba = bb + nt * 16 * STRIDE_B;
                uint32_t bc0, bc1, bc2, bc3, bn0, bn1, bn2, bn3;
                ldsm_x4(bc0, bc1, bc2, bc3, ba);
                #pragma unroll
                for (int kk = 0; kk < 8; kk++) {
                    if (kk < 7) ldsm_x4(bn0, bn1, bn2, bn3, ba + (kk + 1) * 32);
                    const int kh = kk & 1;
                    mma_bf16(acc[0][0][kh], A[0][kk], bc0, bc1);
                    mma_bf16(acc[0][1][kh], A[0][kk], bc2, bc3);
                    mma_bf16(acc[1][0][kh], A[1][kk], bc0, bc1);
                    mma_bf16(acc[1][1][kh], A[1][kk], bc2, bc3);
                    bc0 = bn0; bc1 = bn1; bc2 = bn2; bc3 = bn3;
                }
                const int n0 = nbase + nt * 16;
                #pragma unroll
                for (int c = 0; c < 2; c++) {
                    float2 m = *reinterpret_cast<const float2*>(&m2s[n0 + 8 * c + 2 * tg]);
                    #pragma unroll
                    for (int rg = 0; rg < 2; rg++) {
                        float c0 = fmaf(-2.0f, acc[rg][c][0][0],
                                   fmaf(-2.0f, acc[rg][c][1][0], m.x));
                        float c1 = fmaf(-2.0f, acc[rg][c][0][1],
                                   fmaf(-2.0f, acc[rg][c][1][1], m.y));
                        float c2 = fmaf(-2.0f, acc[rg][c][0][2],
                                   fmaf(-2.0f, acc[rg][c][1][2], m.x));
                        float c3 = fmaf(-2.0f, acc[rg][c][0][3],
                                   fmaf(-2.0f, acc[rg][c][1][3], m.y));
                        mn[rg * 2 + 0] = fminf(mn[rg * 2 + 0], fminf(c0, c1));
                        mn[rg * 2 + 1] = fminf(mn[rg * 2 + 1], fminf(c2, c3));
                    }
                }
            }

            // ---- min across the 4 threads sharing each row ----
            #pragma unroll
            for (int q = 0; q < 4; q++) {
                mn[q] = fminf(mn[q], __shfl_xor_sync(0xffffffffu, mn[q], 1));
                mn[q] = fminf(mn[q], __shfl_xor_sync(0xffffffffu, mn[q], 2));
            }
            if (tg == 0) {
                mhp[(r0 + g)      * 2 + nh] = mn[0];
                mhp[(r0 + g + 8)  * 2 + nh] = mn[1];
                mhp[(r0 + g + 16) * 2 + nh] = mn[2];
                mhp[(r0 + g + 24) * 2 + nh] = mn[3];
            }
            BAR_SYNC(5, 256);                                  // consumers only

            // ---- per-warp: combine halves for 16 rows, sqrt, sum, atomic ----
            {
                const int row = wid * 16 + (lane >> 1);
                const int h   = lane & 1;
                float v = mhp[row * 2 + h];
                v = fminf(v, __shfl_xor_sync(0xffffffffu, v, 1));
                float d = 0.0f;
                if (h == 0) d = sqrtf(fmaxf(z2b[p][row] + v, 0.0f));
                #pragma unroll
                for (int o = 16; o > 0; o >>= 1)
                    d += __shfl_down_sync(0xffffffffu, d, o);
                if (lane == 0) atomicAdd(&g_sum, d);
            }
            BAR_ARRIVE(3 + p, 512);                            // signal empty
        }
    }

    // ---- finalize: last CTA writes the mean and self-cleans globals ----
    __syncthreads();
    if (tid == 0) {
        __threadfence();
        unsigned int c = atomicAdd(&g_cnt, 1u);
        if (c == (unsigned int)(grid - 1)) {
            out[0] = (*(volatile float*)&g_sum) / (float)L;
            g_sum = 0.0f;
            g_cnt = 0u;
            g_tile = 0u;
        }
    }
}

extern "C" void kernel_launch(void* const* d_in, const int* in_sizes, int n_in,
                              void* d_out, int out_size) {
    const float* z  = (const float*)d_in[0];
    const float* mu = (const float*)d_in[1];
    float* out = (float*)d_out;

    int L = in_sizes[0] / KDIM;   // 65536
    int ntiles = L / MT;          // 512

    static int nsm = 0;
    if (nsm == 0) {
        cudaDeviceGetAttribute(&nsm, cudaDevAttrMultiProcessorCount, 0);
        cudaFuncSetAttribute(km_main, cudaFuncAttributeMaxDynamicSharedMemorySize, SMEM_BYTES);
    }
    int grid = (ntiles < nsm) ? ntiles : nsm;

    km_main<<<grid, NTHREADS, SMEM_BYTES>>>(z, mu, out, L, ntiles, grid);
}

// round 9
// speedup vs baseline: 1.0613x; 1.0074x over previous
#include <cuda_runtime.h>
#include <cuda_bf16.h>
#include <cstdint>
#include <math.h>

// KMeansClusteringLoss via warp-specialized bf16 HMMA pipeline (single kernel).
//   cost(l,c) = |mu_c|^2 - 2 <z_l, mu_c>,  d(l) = sqrt(max(|z_l|^2 + min_c cost, 0))
//   out = mean_l d(l)
//
// R9 = best-of merge: R6 consumer core (4 chains, no prefetch) + cheap producer
// z2 pass (1 shfl/thread) + 1-barrier epilogue w/ per-warp atomics + single kernel.

#define KDIM  128
#define CDIM  512
#define MT    128
#define NTHREADS 512       // warps 0-7 consumers, 8-15 producers
#define NQ    256          // centroids per consumer warp

#define STRIDE_B 272       // 128 bf16 (256B) + 16B pad -> conflict-free LDSM

// dynamic smem layout (bytes)
#define SM_MU    0                          // 512 x 272 = 139264
#define SM_Z0    139264                     // 128 x 272
#define SM_Z1    174080                     // 128 x 272
#define SM_M2    208896                     // 512 f32
#define SM_Z2_0  210944                     // 128 f32
#define SM_Z2_1  211456                     // 128 f32
#define SM_MH0   211968                     // 128 x 2 f32
#define SM_MH1   212992                     // 128 x 2 f32
#define SM_PT    214016                     // 2 ints
#define SMEM_BYTES 214048

__device__ float g_sum;            // zero-init at load; self-cleaned each run
__device__ unsigned int g_cnt;
__device__ unsigned int g_tile;

// ---------------- helpers ----------------
__device__ __forceinline__ uint32_t smem_u32(const void* p) {
    uint32_t a;
    asm("{ .reg .u64 t; cvta.to.shared.u64 t, %1; cvt.u32.u64 %0, t; }" : "=r"(a) : "l"(p));
    return a;
}
__device__ __forceinline__ void ldsm_x4(uint32_t& r0, uint32_t& r1, uint32_t& r2, uint32_t& r3,
                                        uint32_t addr) {
    asm volatile("ldmatrix.sync.aligned.m8n8.x4.shared.b16 {%0,%1,%2,%3}, [%4];"
                 : "=r"(r0), "=r"(r1), "=r"(r2), "=r"(r3) : "r"(addr));
}
__device__ __forceinline__ void mma_bf16(float* d, const uint32_t* a,
                                         uint32_t b0, uint32_t b1) {
    asm volatile(
        "mma.sync.aligned.m16n8k16.row.col.f32.bf16.bf16.f32 "
        "{%0,%1,%2,%3}, {%4,%5,%6,%7}, {%8,%9}, {%0,%1,%2,%3};"
        : "+f"(d[0]), "+f"(d[1]), "+f"(d[2]), "+f"(d[3])
        : "r"(a[0]), "r"(a[1]), "r"(a[2]), "r"(a[3]), "r"(b0), "r"(b1));
}
#define BAR_SYNC(id, cnt)   asm volatile("bar.sync %0, %1;"   :: "r"(id), "r"(cnt) : "memory")
#define BAR_ARRIVE(id, cnt) asm volatile("bar.arrive %0, %1;" :: "r"(id), "r"(cnt) : "memory")

// Fill a z tile: global fp32 -> bf16 packed smem (no reductions).
__device__ __forceinline__ void fill_z(const float* __restrict__ z, int tile,
                                       char* smem, int zoff, int t, int nthr) {
    const size_t m0 = (size_t)tile * MT;
    const int iters = (MT * 16) / nthr;
    #pragma unroll
    for (int it = 0; it < iters; it++) {
        int idx = t + it * nthr;
        int row = idx >> 4, kc = idx & 15;
        const float4* p = reinterpret_cast<const float4*>(z + (m0 + row) * KDIM + kc * 8);
        float4 v0 = p[0], v1 = p[1];
        __nv_bfloat162 b0 = __floats2bfloat162_rn(v0.x, v0.y);
        __nv_bfloat162 b1 = __floats2bfloat162_rn(v0.z, v0.w);
        __nv_bfloat162 b2 = __floats2bfloat162_rn(v1.x, v1.y);
        __nv_bfloat162 b3 = __floats2bfloat162_rn(v1.z, v1.w);
        uint4 q;
        q.x = *reinterpret_cast<uint32_t*>(&b0);
        q.y = *reinterpret_cast<uint32_t*>(&b1);
        q.z = *reinterpret_cast<uint32_t*>(&b2);
        q.w = *reinterpret_cast<uint32_t*>(&b3);
        *reinterpret_cast<uint4*>(smem + zoff + row * STRIDE_B + kc * 16) = q;
    }
}

// |z|^2 second pass over a filled tile: 256 threads, 2 per row, 1 shfl.
__device__ __forceinline__ void z2_pass(const char* smem, int zoff, float* z2buf, int pt) {
    const int row = pt >> 1;
    const int half = pt & 1;
    float s = 0.0f;
    #pragma unroll
    for (int j = 0; j < 8; j++) {
        uint4 q = *reinterpret_cast<const uint4*>(smem + zoff + row * STRIDE_B
                                                  + half * 128 + j * 16);
        uint32_t u[4] = {q.x, q.y, q.z, q.w};
        #pragma unroll
        for (int e = 0; e < 4; e++) {
            float lo = __uint_as_float(u[e] << 16);
            float hi = __uint_as_float(u[e] & 0xffff0000u);
            s = fmaf(lo, lo, s);
            s = fmaf(hi, hi, s);
        }
    }
    s += __shfl_xor_sync(0xffffffffu, s, 1);     // pt parity == lane parity
    if (half == 0) z2buf[row] = s;
}

// ---------------- persistent warp-specialized kernel ----------------
__global__ void __launch_bounds__(NTHREADS, 1) km_main(
    const float* __restrict__ z, const float* __restrict__ mu,
    float* __restrict__ out, int L, int ntiles, int grid)
{
    extern __shared__ char smem[];
    const uint32_t sbase = smem_u32(smem);
    float* m2s = reinterpret_cast<float*>(smem + SM_M2);
    float* z2b[2] = { reinterpret_cast<float*>(smem + SM_Z2_0),
                      reinterpret_cast<float*>(smem + SM_Z2_1) };
    float* mhb[2] = { reinterpret_cast<float*>(smem + SM_MH0),
                      reinterpret_cast<float*>(smem + SM_MH1) };
    int* ptile = reinterpret_cast<int*>(smem + SM_PT);

    const int tid  = threadIdx.x;
    const int wid  = tid >> 5;
    const int lane = tid & 31;

    // ---- prologue: steal tile 0; mu fp32->bf16 into smem; m2; fill+z2 buf0 ----
    if (tid == 0) ptile[0] = (int)atomicAdd(&g_tile, 1u);

    #pragma unroll
    for (int it = 0; it < 16; it++) {            // 8192 chunks of 16B (bf16 out)
        int idx = tid + it * NTHREADS;
        int row = idx >> 4, kc = idx & 15;
        const float4* p = reinterpret_cast<const float4*>(mu + row * KDIM + kc * 8);
        float4 v0 = p[0], v1 = p[1];
        __nv_bfloat162 b0 = __floats2bfloat162_rn(v0.x, v0.y);
        __nv_bfloat162 b1 = __floats2bfloat162_rn(v0.z, v0.w);
        __nv_bfloat162 b2 = __floats2bfloat162_rn(v1.x, v1.y);
        __nv_bfloat162 b3 = __floats2bfloat162_rn(v1.z, v1.w);
        uint4 q;
        q.x = *reinterpret_cast<uint32_t*>(&b0);
        q.y = *reinterpret_cast<uint32_t*>(&b1);
        q.z = *reinterpret_cast<uint32_t*>(&b2);
        q.w = *reinterpret_cast<uint32_t*>(&b3);
        *reinterpret_cast<uint4*>(smem + SM_MU + row * STRIDE_B + kc * 16) = q;
    }
    __syncthreads();

    // m2 per centroid from the bf16 values (thread t -> centroid t)
    {
        float s = 0.0f;
        #pragma unroll
        for (int j = 0; j < 16; j++) {
            uint4 q = *reinterpret_cast<const uint4*>(smem + SM_MU + tid * STRIDE_B + j * 16);
            uint32_t u[4] = {q.x, q.y, q.z, q.w};
            #pragma unroll
            for (int e = 0; e < 4; e++) {
                float lo = __uint_as_float(u[e] << 16);
                float hi = __uint_as_float(u[e] & 0xffff0000u);
                s = fmaf(lo, lo, s);
                s = fmaf(hi, hi, s);
            }
        }
        m2s[tid] = s;
    }

    fill_z(z, ptile[0], smem, SM_Z0, tid, NTHREADS);
    __syncthreads();
    if (tid < 256) z2_pass(smem, SM_Z0, z2b[0], tid);
    __syncthreads();

    if (wid >= 8) {
        // ================= PRODUCER (warps 8-15) =================
        const int ptid = tid - 256;
        for (int i = 1;; i++) {
            const int p = i & 1;
            if (i >= 2) BAR_SYNC(3 + p, 512);                 // wait buffer empty
            if (ptid == 0) {
                int t = (int)atomicAdd(&g_tile, 1u);
                ptile[p] = (t < ntiles) ? t : -1;
            }
            BAR_SYNC(6, 256);                                  // ptile visible
            const int t = ptile[p];
            if (t >= 0) {
                const int zoff = p ? SM_Z1 : SM_Z0;
                fill_z(z, t, smem, zoff, ptid, 256);
                BAR_SYNC(6, 256);                              // drain STS before z2 reads
                z2_pass(smem, zoff, z2b[p], ptid);
            }
            __threadfence_block();
            BAR_ARRIVE(1 + p, 512);                            // signal full
            if (t < 0) break;
        }
    } else {
        // ================= CONSUMER (warps 0-7) =================
        const int tg   = lane & 3;
        const int g    = lane >> 2;
        const int rw   = wid & 3;           // row-group (m32)
        const int nh   = wid >> 2;          // centroid half (0/1)
        const int r0   = rw * 32;
        const int nbase = nh * NQ;

        const uint32_t bb = sbase + SM_MU
                          + (lane & 7) * STRIDE_B
                          + (((lane >> 3) & 1) ? 16u : 0u)
                          + (lane >> 4) * 8 * STRIDE_B
                          + nbase * STRIDE_B;

        for (int i = 0;; i++) {
            const int p = i & 1;
            if (i >= 1) BAR_SYNC(1 + p, 512);                  // wait buffer full
            const int t = ptile[p];
            if (t < 0) break;
            const uint32_t zb = sbase + (p ? SM_Z1 : SM_Z0);
            float* mhp = mhb[p];

            // ---- A fragments: m32 x K128 register-resident ----
            uint32_t A[2][8][4];
            {
                const uint32_t ab = zb + (lane & 15) * STRIDE_B
                                  + ((lane & 16) ? 16u : 0u) + r0 * STRIDE_B;
                #pragma unroll
                for (int rg = 0; rg < 2; rg++)
                    #pragma unroll
                    for (int kk = 0; kk < 8; kk++)
                        ldsm_x4(A[rg][kk][0], A[rg][kk][1], A[rg][kk][2], A[rg][kk][3],
                                ab + rg * 16 * STRIDE_B + kk * 32);
            }

            // ---- 256 centroids: 16 iters of n16, 4 indep chains (R6 core) ----
            float mn[4] = {INFINITY, INFINITY, INFINITY, INFINITY};
            #pragma unroll 1
            for (int nt = 0; nt < NQ / 16; nt++) {
                float acc[2][2][4] = {};
                const uint32_t ba = bb + nt * 16 * STRIDE_B;
                #pragma unroll
                for (int kk = 0; kk < 8; kk++) {
                    uint32_t b0, b1, b2, b3;
                    ldsm_x4(b0, b1, b2, b3, ba + kk * 32);
                    mma_bf16(acc[0][0], A[0][kk], b0, b1);
                    mma_bf16(acc[0][1], A[0][kk], b2, b3);
                    mma_bf16(acc[1][0], A[1][kk], b0, b1);
                    mma_bf16(acc[1][1], A[1][kk], b2, b3);
                }
                const int n0 = nbase + nt * 16;
                #pragma unroll
                for (int c = 0; c < 2; c++) {
                    float2 m = *reinterpret_cast<const float2*>(&m2s[n0 + 8 * c + 2 * tg]);
                    #pragma unroll
                    for (int rg = 0; rg < 2; rg++) {
                        mn[rg * 2 + 0] = fminf(mn[rg * 2 + 0], fmaf(-2.0f, acc[rg][c][0], m.x));
                        mn[rg * 2 + 0] = fminf(mn[rg * 2 + 0], fmaf(-2.0f, acc[rg][c][1], m.y));
                        mn[rg * 2 + 1] = fminf(mn[rg * 2 + 1], fmaf(-2.0f, acc[rg][c][2], m.x));
                        mn[rg * 2 + 1] = fminf(mn[rg * 2 + 1], fmaf(-2.0f, acc[rg][c][3], m.y));
                    }
                }
            }

            // ---- min across the 4 threads sharing each row ----
            #pragma unroll
            for (int q = 0; q < 4; q++) {
                mn[q] = fminf(mn[q], __shfl_xor_sync(0xffffffffu, mn[q], 1));
                mn[q] = fminf(mn[q], __shfl_xor_sync(0xffffffffu, mn[q], 2));
            }
            if (tg == 0) {
                mhp[(r0 + g)      * 2 + nh] = mn[0];
                mhp[(r0 + g + 8)  * 2 + nh] = mn[1];
                mhp[(r0 + g + 16) * 2 + nh] = mn[2];
                mhp[(r0 + g + 24) * 2 + nh] = mn[3];
            }
            BAR_SYNC(5, 256);                                  // consumers only

            // ---- per-warp: combine halves for 16 rows, sqrt, sum, atomic ----
            {
                const int row = wid * 16 + (lane >> 1);
                const int h   = lane & 1;
                float v = mhp[row * 2 + h];
                v = fminf(v, __shfl_xor_sync(0xffffffffu, v, 1));
                float d = 0.0f;
                if (h == 0) d = sqrtf(fmaxf(z2b[p][row] + v, 0.0f));
                #pragma unroll
                for (int o = 16; o > 0; o >>= 1)
                    d += __shfl_down_sync(0xffffffffu, d, o);
                if (lane == 0) atomicAdd(&g_sum, d);
            }
            BAR_ARRIVE(3 + p, 512);                            // signal empty
        }
    }

    // ---- finalize: last CTA writes the mean and self-cleans globals ----
    __syncthreads();
    if (tid == 0) {
        __threadfence();
        unsigned int c = atomicAdd(&g_cnt, 1u);
        if (c == (unsigned int)(grid - 1)) {
            out[0] = (*(volatile float*)&g_sum) / (float)L;
            g_sum = 0.0f;
            g_cnt = 0u;
            g_tile = 0u;
        }
    }
}

extern "C" void kernel_launch(void* const* d_in, const int* in_sizes, int n_in,
                              void* d_out, int out_size) {
    const float* z  = (const float*)d_in[0];
    const float* mu = (const float*)d_in[1];
    float* out = (float*)d_out;

    int L = in_sizes[0] / KDIM;   // 65536
    int ntiles = L / MT;          // 512

    static int nsm = 0;
    if (nsm == 0) {
        cudaDeviceGetAttribute(&nsm, cudaDevAttrMultiProcessorCount, 0);
        cudaFuncSetAttribute(km_main, cudaFuncAttributeMaxDynamicSharedMemorySize, SMEM_BYTES);
    }
    int grid = (ntiles < nsm) ? ntiles : nsm;

    km_main<<<grid, NTHREADS, SMEM_BYTES>>>(z, mu, out, L, ntiles, grid);
}